// round 9
// baseline (speedup 1.0000x reference)
#include <cuda_runtime.h>
#include <cuda_bf16.h>

#define WARPS_PER_BLOCK 8
#define THREADS_PER_BLOCK (WARPS_PER_BLOCK * 32)

static __device__ __forceinline__ float merge_f(float a, float b, int w, int lane) {
    const unsigned FULL = 0xffffffffu;
    const float keep = (lane & w) ? b : a;
    const float send = (lane & w) ? a : b;
    return keep + __shfl_xor_sync(FULL, send, w);
}

// One warp per batch row. D=128 floats (row = 32 float4). K=32 (hardwired).
// Half-warp layout: 2 halves (16 lanes); slot s (0..15): half h handles
// candidate c = 2s+h, its 512B row read as 2 x 256B chunks. Reductions
// deferred to group boundaries (4 groups x 4 slots); body = pure LDG+FMA.
// __launch_bounds__(.,5) caps regs at ~51 -> 5 CTAs/SM (40 warps).
__global__ __launch_bounds__(THREADS_PER_BLOCK, 5)
void intra_agg_kernel(const float* __restrict__ features,
                      const int*   __restrict__ nodes,
                      const int*   __restrict__ neighs,
                      const int*   __restrict__ nsamp,
                      float*       __restrict__ out,
                      int B)
{
    const unsigned FULL = 0xffffffffu;
    const int lane = threadIdx.x & 31;
    const int row  = blockIdx.x * WARPS_PER_BLOCK + (threadIdx.x >> 5);
    if (row >= B) return;

    const int ns = nsamp ? nsamp[0] : 10;

    const float4* __restrict__ F = reinterpret_cast<const float4*>(features);
    const int* __restrict__ nrow = neighs + (size_t)row * 32;

    const int my_neigh = nrow[lane];              // lane k owns candidate k
    const int half = lane >> 4;                   // 0,1
    const int hl   = lane & 15;                   // lane within half

    // center row in half-chunk layout: cc[t] = float4 index t*16 + hl
    const float4* cbase = F + (size_t)nodes[row] * 32 + hl;
    float4 cc[2];
    cc[0] = cbase[0];
    cc[1] = cbase[16];

    float my_dot = 0.0f;
    float my_n2  = 1.0f;

    // redistribute source lane is g-independent (bits of own lane only)
    const int rsrc = ((lane & 1) << 4) | (((lane >> 1) & 1) << 2) | (((lane >> 2) & 1) << 3);

    // ---- Phase 1: 4 groups x 4 slots; body = pure LDG+FMA ----
    #pragma unroll
    for (int g = 0; g < 4; g++) {
        int cidx[4];
        #pragma unroll
        for (int u = 0; u < 4; u++)   // candidate c = 8g + 2u + half
            cidx[u] = __shfl_sync(FULL, my_neigh, 8 * g + 2 * u + half);

        float dp[4], np[4];
        #pragma unroll
        for (int u = 0; u < 4; u++) {
            const float4* base = F + (size_t)cidx[u] * 32 + hl;
            const float4 f0 = base[0];
            const float4 f1 = base[16];

            float d = 0.0f, n = 0.0f;
            d = fmaf(cc[0].x, f0.x, d);
            d = fmaf(cc[0].y, f0.y, d);
            d = fmaf(cc[0].z, f0.z, d);
            d = fmaf(cc[0].w, f0.w, d);
            d = fmaf(cc[1].x, f1.x, d);
            d = fmaf(cc[1].y, f1.y, d);
            d = fmaf(cc[1].z, f1.z, d);
            d = fmaf(cc[1].w, f1.w, d);
            n = fmaf(f0.x, f0.x, n);
            n = fmaf(f0.y, f0.y, n);
            n = fmaf(f0.z, f0.z, n);
            n = fmaf(f0.w, f0.w, n);
            n = fmaf(f1.x, f1.x, n);
            n = fmaf(f1.y, f1.y, n);
            n = fmaf(f1.z, f1.z, n);
            n = fmaf(f1.w, f1.w, n);
            dp[u] = d; np[u] = n;
        }

        // 16-lane transpose-reduce of 4 values (lane hl ends holding
        // value v = bit2(hl) + 2*bit3(hl), full sum over its half)
        float hd, hn;
        {
            float e0 = merge_f(dp[0], dp[2], 8, lane);
            float e1 = merge_f(dp[1], dp[3], 8, lane);
            float h  = merge_f(e0, e1, 4, lane);
            h += __shfl_xor_sync(FULL, h, 2);
            h += __shfl_xor_sync(FULL, h, 1);
            hd = h;
        }
        {
            float e0 = merge_f(np[0], np[2], 8, lane);
            float e1 = merge_f(np[1], np[3], 8, lane);
            float h  = merge_f(e0, e1, 4, lane);
            h += __shfl_xor_sync(FULL, h, 2);
            h += __shfl_xor_sync(FULL, h, 1);
            hn = h;
        }

        // deliver: lane L owns candidate L = 8g + 2u + h with g = L>>3
        const float db = __shfl_sync(FULL, hd, rsrc);
        const float nb = __shfl_sync(FULL, hn, rsrc);
        if ((lane >> 3) == g) { my_dot = db; my_n2 = nb; }
    }

    // key = dot / ||neigh||  (center norm: common positive factor, dropped)
    float r = rsqrtf(my_n2);
    r = r * fmaf(-0.5f * my_n2, r * r, 1.5f);     // Newton -> ~fp32-exact
    const float my_key = my_dot * r;

    // ---- stable rank-by-counting (matches jax.lax.top_k tie-break) ----
    int rank = 0;
    #pragma unroll
    for (int j = 0; j < 32; j++) {
        const float kj = __shfl_sync(FULL, my_key, j);
        rank += (kj > my_key) || (kj == my_key && j < lane);
    }

    // ---- Phase 2: mean over selected neighbors ----
    const unsigned sel = __ballot_sync(FULL, rank < ns);
    float4 acc = make_float4(0.f, 0.f, 0.f, 0.f);

    if (ns == 10) {
        int src10[10];
        unsigned m = sel;
        #pragma unroll
        for (int i = 0; i < 10; i++) { src10[i] = __ffs(m) - 1; m &= m - 1; }
        int nid[10];
        #pragma unroll
        for (int i = 0; i < 10; i++) nid[i] = __shfl_sync(FULL, my_neigh, src10[i]);
        #pragma unroll
        for (int s0 = 0; s0 < 10; s0 += 5) {
            float4 v[5];
            #pragma unroll
            for (int u = 0; u < 5; u++)
                v[u] = F[(size_t)nid[s0 + u] * 32 + lane];
            #pragma unroll
            for (int u = 0; u < 5; u++) {
                acc.x += v[u].x; acc.y += v[u].y;
                acc.z += v[u].z; acc.w += v[u].w;
            }
        }
    } else {
        unsigned m = sel;
        while (m) {
            const int j = __ffs(m) - 1;
            m &= m - 1;
            const int nidx = __shfl_sync(FULL, my_neigh, j);
            const float4 v = F[(size_t)nidx * 32 + lane];
            acc.x += v.x; acc.y += v.y; acc.z += v.z; acc.w += v.w;
        }
    }

    const float inv = 1.0f / (float)ns;
    float4 o;
    o.x = fmaxf(acc.x * inv, 0.0f);
    o.y = fmaxf(acc.y * inv, 0.0f);
    o.z = fmaxf(acc.z * inv, 0.0f);
    o.w = fmaxf(acc.w * inv, 0.0f);
    __stcs(reinterpret_cast<float4*>(out) + (size_t)row * 32 + lane, o);
}

extern "C" void kernel_launch(void* const* d_in, const int* in_sizes, int n_in,
                              void* d_out, int out_size)
{
    const float* features = (const float*)d_in[0];
    const int*   nodes    = (const int*)d_in[1];
    const int*   neighs   = (const int*)d_in[2];
    const int*   nsamp    = (n_in >= 4) ? (const int*)d_in[3] : nullptr;
    float*       out      = (float*)d_out;

    const int B = in_sizes[1];

    const int blocks = (B + WARPS_PER_BLOCK - 1) / WARPS_PER_BLOCK;
    intra_agg_kernel<<<blocks, THREADS_PER_BLOCK>>>(features, nodes, neighs, nsamp,
                                                    out, B);
}

// round 10
// speedup vs baseline: 1.0963x; 1.0963x over previous
#include <cuda_runtime.h>
#include <cuda_bf16.h>

#define WARPS_PER_BLOCK 8
#define THREADS_PER_BLOCK (WARPS_PER_BLOCK * 32)

static __device__ __forceinline__ float merge_f(float a, float b, int w, int lane) {
    const unsigned FULL = 0xffffffffu;
    const float keep = (lane & w) ? b : a;
    const float send = (lane & w) ? a : b;
    return keep + __shfl_xor_sync(FULL, send, w);
}

// One warp per batch row. D=128 floats (row = 32 float4). K=32 (hardwired).
// Octet layout: 4 octets (8 lanes); slot s (0..7): octet o handles candidate
// c = 4s+o, its 512B row read as 4 x 128B chunks (4 lines per LDG.128).
// ALL reductions deferred past the full 8-slot body (pure LDG+FMA -> maximal
// load batching), then one in-octet 3-level transpose-reduce.
__global__ __launch_bounds__(THREADS_PER_BLOCK, 4)
void intra_agg_kernel(const float* __restrict__ features,
                      const int*   __restrict__ nodes,
                      const int*   __restrict__ neighs,
                      const int*   __restrict__ nsamp,
                      float*       __restrict__ out,
                      int B)
{
    const unsigned FULL = 0xffffffffu;
    const int lane = threadIdx.x & 31;
    const int row  = blockIdx.x * WARPS_PER_BLOCK + (threadIdx.x >> 5);
    if (row >= B) return;

    const int ns = nsamp ? nsamp[0] : 10;

    const float4* __restrict__ F = reinterpret_cast<const float4*>(features);
    const int* __restrict__ nrow = neighs + (size_t)row * 32;

    const int my_neigh = nrow[lane];              // lane k owns candidate k
    const int oct      = lane >> 3;               // my octet (0..3)
    const int ol       = lane & 7;                // lane within octet

    // center row in octet-chunk layout: cc[t] = float4 index t*8 + ol
    const float4* cbase = F + (size_t)nodes[row] * 32 + ol;
    float4 cc[4];
    #pragma unroll
    for (int t = 0; t < 4; t++) cc[t] = cbase[t * 8];

    // ---- Phase 1: 8 slots, pure LDG+FMA (no shfl in the body at all) ----
    const int* __restrict__ ibase = nrow + oct;   // index for slot s at ibase[4*s]
    float dp[8], np[8];
    #pragma unroll
    for (int s = 0; s < 8; s++) {
        const int cidx = __ldg(&ibase[4 * s]);    // 1 line, broadcast per octet
        const float4* base = F + (size_t)cidx * 32 + ol;
        float4 f[4];
        #pragma unroll
        for (int t = 0; t < 4; t++) f[t] = base[t * 8];

        float d = 0.0f, n = 0.0f;
        #pragma unroll
        for (int t = 0; t < 4; t++) {
            d = fmaf(cc[t].x, f[t].x, d);
            d = fmaf(cc[t].y, f[t].y, d);
            d = fmaf(cc[t].z, f[t].z, d);
            d = fmaf(cc[t].w, f[t].w, d);
            n = fmaf(f[t].x, f[t].x, n);
            n = fmaf(f[t].y, f[t].y, n);
            n = fmaf(f[t].z, f[t].z, n);
            n = fmaf(f[t].w, f[t].w, n);
        }
        dp[s] = d; np[s] = n;
    }

    // ---- One in-octet transpose-reduce of 8 values (3 levels: w=4,2,1).
    // Afterwards lane ol holds the full octet-sum of slot v = ol&7,
    // i.e. candidate 4*ol+oct lives at warp lane 8*oct+ol. ----
    float my_dot, my_n2;
    {
        float e0 = merge_f(dp[0], dp[4], 4, lane);
        float e1 = merge_f(dp[1], dp[5], 4, lane);
        float e2 = merge_f(dp[2], dp[6], 4, lane);
        float e3 = merge_f(dp[3], dp[7], 4, lane);
        float h0 = merge_f(e0, e2, 2, lane);
        float h1 = merge_f(e1, e3, 2, lane);
        float q  = merge_f(h0, h1, 1, lane);
        // owner lane L (candidate L = 4s+o): s=L>>2 held at lane 8*(L&3)+(L>>2)
        my_dot = __shfl_sync(FULL, q, ((lane & 3) << 3) + (lane >> 2));
    }
    {
        float e0 = merge_f(np[0], np[4], 4, lane);
        float e1 = merge_f(np[1], np[5], 4, lane);
        float e2 = merge_f(np[2], np[6], 4, lane);
        float e3 = merge_f(np[3], np[7], 4, lane);
        float h0 = merge_f(e0, e2, 2, lane);
        float h1 = merge_f(e1, e3, 2, lane);
        float q  = merge_f(h0, h1, 1, lane);
        my_n2 = __shfl_sync(FULL, q, ((lane & 3) << 3) + (lane >> 2));
    }

    // key = dot / ||neigh||  (center norm: common positive factor, dropped)
    float r = rsqrtf(my_n2);
    r = r * fmaf(-0.5f * my_n2, r * r, 1.5f);     // Newton -> ~fp32-exact
    const float my_key = my_dot * r;

    // ---- stable rank-by-counting (matches jax.lax.top_k tie-break) ----
    int rank = 0;
    #pragma unroll
    for (int j = 0; j < 32; j++) {
        const float kj = __shfl_sync(FULL, my_key, j);
        rank += (kj > my_key) || (kj == my_key && j < lane);
    }

    // ---- Phase 2: mean over selected neighbors ----
    const unsigned sel = __ballot_sync(FULL, rank < ns);
    float4 acc = make_float4(0.f, 0.f, 0.f, 0.f);

    if (ns == 10) {
        int src10[10];
        unsigned m = sel;
        #pragma unroll
        for (int i = 0; i < 10; i++) { src10[i] = __ffs(m) - 1; m &= m - 1; }
        int nid[10];
        #pragma unroll
        for (int i = 0; i < 10; i++) nid[i] = __shfl_sync(FULL, my_neigh, src10[i]);
        #pragma unroll
        for (int s0 = 0; s0 < 10; s0 += 5) {
            float4 v[5];
            #pragma unroll
            for (int u = 0; u < 5; u++)
                v[u] = F[(size_t)nid[s0 + u] * 32 + lane];
            #pragma unroll
            for (int u = 0; u < 5; u++) {
                acc.x += v[u].x; acc.y += v[u].y;
                acc.z += v[u].z; acc.w += v[u].w;
            }
        }
    } else {
        unsigned m = sel;
        while (m) {
            const int j = __ffs(m) - 1;
            m &= m - 1;
            const int nidx = __shfl_sync(FULL, my_neigh, j);
            const float4 v = F[(size_t)nidx * 32 + lane];
            acc.x += v.x; acc.y += v.y; acc.z += v.z; acc.w += v.w;
        }
    }

    const float inv = 1.0f / (float)ns;
    float4 o;
    o.x = fmaxf(acc.x * inv, 0.0f);
    o.y = fmaxf(acc.y * inv, 0.0f);
    o.z = fmaxf(acc.z * inv, 0.0f);
    o.w = fmaxf(acc.w * inv, 0.0f);
    __stcs(reinterpret_cast<float4*>(out) + (size_t)row * 32 + lane, o);
}

extern "C" void kernel_launch(void* const* d_in, const int* in_sizes, int n_in,
                              void* d_out, int out_size)
{
    const float* features = (const float*)d_in[0];
    const int*   nodes    = (const int*)d_in[1];
    const int*   neighs   = (const int*)d_in[2];
    const int*   nsamp    = (n_in >= 4) ? (const int*)d_in[3] : nullptr;
    float*       out      = (float*)d_out;

    const int B = in_sizes[1];

    const int blocks = (B + WARPS_PER_BLOCK - 1) / WARPS_PER_BLOCK;
    intra_agg_kernel<<<blocks, THREADS_PER_BLOCK>>>(features, nodes, neighs, nsamp,
                                                    out, B);
}